// round 3
// baseline (speedup 1.0000x reference)
#include <cuda_runtime.h>
#include <cstdint>

#define Bm 128
#define NAc 48
#define NBc 96
#define Hc 200
#define AFc 39
#define BFc 50      // ATOM_FDIM + BOND_FDIM
#define Lc 1000

// ---------------- scratch (device globals; no allocation) ----------------
__device__ float g_binput[Bm * NBc * Hc];
__device__ float g_message[Bm * NBc * Hc];
__device__ float g_emb[Bm * Hc];
__device__ float g_prot[Bm * Hc];          // protein max-pool accum (relu >= 0)
__device__ float g_pv0[Bm * 50 * Lc];
__device__ float g_pv1[Bm * 96 * Lc];
__device__ float g_pv2[Bm * 128 * Lc];

// ---------------- init: zero the atomicMax accumulator -------------------
__global__ void k_zero_prot() {
    int i = blockIdx.x * blockDim.x + threadIdx.x;
    if (i < Bm * Hc) g_prot[i] = 0.f;
}

// ---------------- MPNN: binput = fbonds @ W_i; message = relu ------------
__global__ void k_binput(const float* __restrict__ fb, const float* __restrict__ Wi) {
    extern __shared__ float sm[];
    float* sF = sm;                 // NBc*BFc = 4800
    float* sW = sm + NBc * BFc;     // BFc*Hc  = 10000
    int b = blockIdx.x, tid = threadIdx.x;
    const float* fbB = fb + (size_t)b * NBc * BFc;
    for (int i = tid; i < NBc * BFc; i += blockDim.x) sF[i] = fbB[i];
    for (int i = tid; i < BFc * Hc; i += blockDim.x) sW[i] = Wi[i];
    __syncthreads();
    for (int o = tid; o < NBc * Hc; o += blockDim.x) {
        int nb = o / Hc, h = o - nb * Hc;
        float a = 0.f;
        #pragma unroll 5
        for (int k = 0; k < BFc; k++) a += sF[nb * BFc + k] * sW[k * Hc + h];
        int idx = b * NBc * Hc + o;
        g_binput[idx] = a;
        g_message[idx] = fmaxf(a, 0.f);
    }
}

// ---------------- MPNN: one message-passing iteration ---------------------
__global__ void k_iter(const int* __restrict__ bgraph, const float* __restrict__ Wh) {
    extern __shared__ float sm[];
    float* sMsg = sm;                // NBc*Hc = 19200
    float* sNei = sm + NBc * Hc;     // NBc*Hc
    int b = blockIdx.x, tid = threadIdx.x;
    const float* msgB = g_message + (size_t)b * NBc * Hc;
    for (int i = tid; i < NBc * Hc; i += blockDim.x) sMsg[i] = msgB[i];
    __syncthreads();
    // neighbor gather-sum
    for (int o = tid; o < NBc * Hc; o += blockDim.x) {
        int nb = o / Hc, h = o - nb * Hc;
        const int* bg = bgraph + (b * NBc + nb) * 6;
        float s = 0.f;
        #pragma unroll
        for (int j = 0; j < 6; j++) s += sMsg[bg[j] * Hc + h];
        sNei[o] = s;
    }
    __syncthreads();
    // message = relu(binput + nei @ W_h), 8-row register blocking
    for (int o = tid; o < (NBc / 8) * Hc; o += blockDim.x) {
        int g = o / Hc, h = o - g * Hc;
        int nb0 = g * 8;
        float acc[8] = {0, 0, 0, 0, 0, 0, 0, 0};
        for (int k = 0; k < Hc; k++) {
            float wv = Wh[k * Hc + h];
            #pragma unroll
            for (int j = 0; j < 8; j++) acc[j] += sNei[(nb0 + j) * Hc + k] * wv;
        }
        #pragma unroll
        for (int j = 0; j < 8; j++) {
            int idx = b * NBc * Hc + (nb0 + j) * Hc + h;
            g_message[idx] = fmaxf(g_binput[idx] + acc[j], 0.f);
        }
    }
}

// ---------------- MPNN: atom output + mean -> molecule embedding ----------
__global__ void k_out(const int* __restrict__ agraph, const float* __restrict__ fa,
                      const float* __restrict__ Wo, const float* __restrict__ Wob) {
    extern __shared__ float sm[];
    float* sMsg = sm;                         // NBc*Hc (reused as sAtom later)
    float* sNei = sm + NBc * Hc;              // NAc*Hc = 9600
    float* sFa  = sNei + NAc * Hc;            // NAc*AFc = 1872
    int b = blockIdx.x, tid = threadIdx.x;
    const float* msgB = g_message + (size_t)b * NBc * Hc;
    for (int i = tid; i < NBc * Hc; i += blockDim.x) sMsg[i] = msgB[i];
    const float* faB = fa + (size_t)b * NAc * AFc;
    for (int i = tid; i < NAc * AFc; i += blockDim.x) sFa[i] = faB[i];
    __syncthreads();
    for (int o = tid; o < NAc * Hc; o += blockDim.x) {
        int na = o / Hc, h = o - na * Hc;
        const int* ag = agraph + (b * NAc + na) * 6;
        float s = 0.f;
        #pragma unroll
        for (int j = 0; j < 6; j++) s += sMsg[ag[j] * Hc + h];
        sNei[o] = s;
    }
    __syncthreads();
    // atom_h = relu([fa, nei] @ W_o + b)  (write into sMsg region)
    for (int o = tid; o < NAc * Hc; o += blockDim.x) {
        int na = o / Hc, h = o - na * Hc;
        float a = Wob[h];
        for (int k = 0; k < AFc; k++) a += sFa[na * AFc + k] * Wo[k * Hc + h];
        for (int k = 0; k < Hc; k++) a += sNei[na * Hc + k] * Wo[(AFc + k) * Hc + h];
        sMsg[o] = fmaxf(a, 0.f);
    }
    __syncthreads();
    for (int h = tid; h < Hc; h += blockDim.x) {
        float s = 0.f;
        for (int na = 0; na < NAc; na++) s += sMsg[na * Hc + h];
        g_emb[b * Hc + h] = s * (1.f / NAc);
    }
}

// ---------------- protein embedding gather -------------------------------
__global__ void k_embed(const int* __restrict__ seq, const float* __restrict__ E) {
    int i = blockIdx.x * blockDim.x + threadIdx.x;
    if (i >= Bm * 50 * Lc) return;
    int b = i / (50 * Lc);
    int r = i - b * (50 * Lc);
    int c = r / Lc;
    int l = r - c * Lc;
    int s = seq[b * Lc + l];
    g_pv0[i] = E[s * 50 + c];
}

// ---------------- generic conv1d + relu (+fused global max) --------------
template <int CIN, int COUT, int K, bool MAXPOOL>
__global__ void conv_kernel(const float* __restrict__ in, const float* __restrict__ w,
                            const float* __restrict__ bias, float* __restrict__ out,
                            float* __restrict__ pmax) {
    constexpr int TL = 128, CoT = 32, PAD = K / 2, TLH = TL + K - 1;
    extern __shared__ float sm[];
    float* sIn = sm;                       // CIN*TLH
    float* sW  = sm + CIN * TLH;           // CoT*CIN*K
    float* sB  = sW + CoT * CIN * K;       // CoT
    int b = blockIdx.z;
    int coBase = blockIdx.y * CoT;
    int lBase = blockIdx.x * TL;
    int tid = threadIdx.x;

    const float* inB = in + (size_t)b * CIN * Lc;
    for (int i = tid; i < CIN * TLH; i += blockDim.x) {
        int ci = i / TLH, p = i - ci * TLH;
        int gl = lBase - PAD + p;
        sIn[i] = (gl >= 0 && gl < Lc) ? inB[ci * Lc + gl] : 0.f;
    }
    for (int i = tid; i < CoT * CIN * K; i += blockDim.x) {
        int coL = i / (CIN * K);
        int rem = i - coL * (CIN * K);
        int co = coBase + coL;
        sW[i] = (co < COUT) ? w[(size_t)co * CIN * K + rem] : 0.f;
    }
    if (tid < CoT) sB[tid] = (coBase + tid < COUT) ? bias[coBase + tid] : 0.f;
    __syncthreads();

    int tco = tid >> 5;        // 0..7 -> 4-co sub-block
    int tl = tid & 31;
    float acc[4][4];
    #pragma unroll
    for (int i = 0; i < 4; i++) {
        float bv = sB[tco * 4 + i];
        #pragma unroll
        for (int j = 0; j < 4; j++) acc[i][j] = bv;
    }

    for (int ci = 0; ci < CIN; ci++) {
        const float* sI = sIn + ci * TLH + tl;
        const float* sWc = sW + ((size_t)(tco * 4) * CIN + ci) * K;
        #pragma unroll
        for (int t = 0; t < K; t++) {
            float w0 = sWc[t];
            float w1 = sWc[CIN * K + t];
            float w2 = sWc[2 * CIN * K + t];
            float w3 = sWc[3 * CIN * K + t];
            float x0 = sI[t], x1 = sI[32 + t], x2 = sI[64 + t], x3 = sI[96 + t];
            acc[0][0] += w0 * x0; acc[0][1] += w0 * x1; acc[0][2] += w0 * x2; acc[0][3] += w0 * x3;
            acc[1][0] += w1 * x0; acc[1][1] += w1 * x1; acc[1][2] += w1 * x2; acc[1][3] += w1 * x3;
            acc[2][0] += w2 * x0; acc[2][1] += w2 * x1; acc[2][2] += w2 * x2; acc[2][3] += w2 * x3;
            acc[3][0] += w3 * x0; acc[3][1] += w3 * x1; acc[3][2] += w3 * x2; acc[3][3] += w3 * x3;
        }
    }

    #pragma unroll
    for (int i = 0; i < 4; i++) {
        int co = coBase + tco * 4 + i;
        if (co < COUT) {
            if (MAXPOOL) {
                float m = 0.f;
                #pragma unroll
                for (int j = 0; j < 4; j++) {
                    int l = lBase + tl + j * 32;
                    if (l < Lc) m = fmaxf(m, fmaxf(acc[i][j], 0.f));
                }
                #pragma unroll
                for (int off = 16; off; off >>= 1)
                    m = fmaxf(m, __shfl_xor_sync(0xffffffffu, m, off));
                if (tl == 0)
                    atomicMax((int*)(pmax + b * COUT + co), __float_as_int(m));
            } else {
                #pragma unroll
                for (int j = 0; j < 4; j++) {
                    int l = lBase + tl + j * 32;
                    if (l < Lc)
                        out[((size_t)b * COUT + co) * Lc + l] = fmaxf(acc[i][j], 0.f);
                }
            }
        }
    }
}

// ---------------- FC head: 400 -> 200 -> 100 -> 1 ------------------------
__global__ void k_fc(const float* __restrict__ w0, const float* __restrict__ b0,
                     const float* __restrict__ w1, const float* __restrict__ b1,
                     const float* __restrict__ w2, const float* __restrict__ b2,
                     float* __restrict__ out) {
    __shared__ float sx[400];
    __shared__ float sy0[200];
    __shared__ float sy1[100];
    int b = blockIdx.x, tid = threadIdx.x;
    for (int k = tid; k < 400; k += blockDim.x)
        sx[k] = (k < 200) ? g_emb[b * 200 + k] : g_prot[b * 200 + (k - 200)];
    __syncthreads();
    for (int j = tid; j < 200; j += blockDim.x) {
        float a = b0[j];
        for (int k = 0; k < 400; k++) a += sx[k] * w0[k * 200 + j];
        sy0[j] = fmaxf(a, 0.f);
    }
    __syncthreads();
    for (int j = tid; j < 100; j += blockDim.x) {
        float a = b1[j];
        for (int k = 0; k < 200; k++) a += sy0[k] * w1[k * 100 + j];
        sy1[j] = fmaxf(a, 0.f);
    }
    __syncthreads();
    if (tid == 0) {
        float a = b2[0];
        for (int k = 0; k < 100; k++) a += sy1[k] * w2[k];
        out[b] = a;
    }
}

// ---------------- launch --------------------------------------------------
extern "C" void kernel_launch(void* const* d_in, const int* in_sizes, int n_in,
                              void* d_out, int out_size) {
    const float* fatoms = (const float*)d_in[0];
    const float* fbonds = (const float*)d_in[1];
    const int* agraph = (const int*)d_in[2];
    const int* bgraph = (const int*)d_in[3];
    const int* pseq = (const int*)d_in[4];
    const float* W_i = (const float*)d_in[5];
    const float* W_h = (const float*)d_in[6];
    const float* W_o_w = (const float*)d_in[7];
    const float* W_o_b = (const float*)d_in[8];
    const float* Ep = (const float*)d_in[9];
    const float* c0w = (const float*)d_in[10];
    const float* c0b = (const float*)d_in[11];
    const float* c1w = (const float*)d_in[12];
    const float* c1b = (const float*)d_in[13];
    const float* c2w = (const float*)d_in[14];
    const float* c2b = (const float*)d_in[15];
    const float* f0w = (const float*)d_in[16];
    const float* f0b = (const float*)d_in[17];
    const float* f1w = (const float*)d_in[18];
    const float* f1b = (const float*)d_in[19];
    const float* f2w = (const float*)d_in[20];
    const float* f2b = (const float*)d_in[21];
    float* out = (float*)d_out;

    // dynamic smem sizes
    const int smem_binput = (NBc * BFc + BFc * Hc) * 4;                  // 59200
    const int smem_iter = 2 * NBc * Hc * 4;                              // 153600
    const int smem_out = (NBc * Hc + NAc * Hc + NAc * AFc) * 4;          // 122688
    const int smem_c0 = (50 * 130 + 32 * 50 * 3 + 32) * 4;               // 45328
    const int smem_c1 = (96 * 132 + 32 * 96 * 5 + 32) * 4;               // 112384
    const int smem_c2 = (128 * 134 + 32 * 128 * 7 + 32) * 4;             // 183424

    // Resolve the REAL device addresses of the __device__ scratch globals.
    // (Passing the symbol directly from host code passes the host shadow
    //  address, which on GB300 is ATS-dereferenceable -> silent wrong data.)
    // Lazy init: first (non-captured) correctness call resolves and caches;
    // zero CUDA API calls happen during graph capture.
    static float *p_pv0 = nullptr, *p_pv1 = nullptr, *p_pv2 = nullptr, *p_prot = nullptr;
    static bool attrs_set = false;
    if (!attrs_set) {
        cudaGetSymbolAddress((void**)&p_pv0, g_pv0);
        cudaGetSymbolAddress((void**)&p_pv1, g_pv1);
        cudaGetSymbolAddress((void**)&p_pv2, g_pv2);
        cudaGetSymbolAddress((void**)&p_prot, g_prot);
        cudaFuncSetAttribute(k_binput, cudaFuncAttributeMaxDynamicSharedMemorySize, smem_binput);
        cudaFuncSetAttribute(k_iter, cudaFuncAttributeMaxDynamicSharedMemorySize, smem_iter);
        cudaFuncSetAttribute(k_out, cudaFuncAttributeMaxDynamicSharedMemorySize, smem_out);
        cudaFuncSetAttribute(conv_kernel<50, 96, 3, false>, cudaFuncAttributeMaxDynamicSharedMemorySize, smem_c0);
        cudaFuncSetAttribute(conv_kernel<96, 128, 5, false>, cudaFuncAttributeMaxDynamicSharedMemorySize, smem_c1);
        cudaFuncSetAttribute(conv_kernel<128, 200, 7, true>, cudaFuncAttributeMaxDynamicSharedMemorySize, smem_c2);
        attrs_set = true;
    }

    // init protein max accumulator
    k_zero_prot<<<(Bm * Hc + 255) / 256, 256>>>();

    // MPNN
    k_binput<<<Bm, 256, smem_binput>>>(fbonds, W_i);
    k_iter<<<Bm, 256, smem_iter>>>(bgraph, W_h);
    k_iter<<<Bm, 256, smem_iter>>>(bgraph, W_h);
    k_out<<<Bm, 256, smem_out>>>(agraph, fatoms, W_o_w, W_o_b);

    // protein tower
    k_embed<<<(Bm * 50 * Lc + 255) / 256, 256>>>(pseq, Ep);
    {
        dim3 g((Lc + 127) / 128, (96 + 31) / 32, Bm);
        conv_kernel<50, 96, 3, false><<<g, 256, smem_c0>>>(p_pv0, c0w, c0b, p_pv1, nullptr);
    }
    {
        dim3 g((Lc + 127) / 128, (128 + 31) / 32, Bm);
        conv_kernel<96, 128, 5, false><<<g, 256, smem_c1>>>(p_pv1, c1w, c1b, p_pv2, nullptr);
    }
    {
        dim3 g((Lc + 127) / 128, (200 + 31) / 32, Bm);
        conv_kernel<128, 200, 7, true><<<g, 256, smem_c2>>>(p_pv2, c2w, c2b, nullptr, p_prot);
    }

    // FC head
    k_fc<<<Bm, 256>>>(f0w, f0b, f1w, f1b, f2w, f2b, out);
}

// round 4
// speedup vs baseline: 1.4127x; 1.4127x over previous
#include <cuda_runtime.h>
#include <cstdint>

#define Bm 128
#define NAc 48
#define NBc 96
#define Hc 200
#define AFc 39
#define BFc 50      // ATOM_FDIM + BOND_FDIM
#define Lc 1000
#define Mrows (Bm * NBc)   // 12288

typedef unsigned long long u64;

// ---------------- f32x2 helpers (sm_103a FFMA2 via PTX) -------------------
__device__ __forceinline__ u64 pack2(float a, float b) {
    u64 r; asm("mov.b64 %0, {%1, %2};" : "=l"(r) : "f"(a), "f"(b)); return r;
}
__device__ __forceinline__ float2 unpack2(u64 a) {
    float2 v; asm("mov.b64 {%0, %1}, %2;" : "=f"(v.x), "=f"(v.y) : "l"(a)); return v;
}
__device__ __forceinline__ u64 ffma2(u64 a, u64 b, u64 c) {
    u64 d; asm("fma.rn.f32x2 %0, %1, %2, %3;" : "=l"(d) : "l"(a), "l"(b), "l"(c)); return d;
}
__device__ __forceinline__ u64 add2(u64 a, u64 b) {
    u64 d; asm("add.rn.f32x2 %0, %1, %2;" : "=l"(d) : "l"(a), "l"(b)); return d;
}

// ---------------- scratch (device globals; no allocation) ----------------
__device__ float g_binput[Mrows * Hc];
__device__ float g_message[Mrows * Hc];
__device__ float g_nei[Mrows * Hc];
__device__ float g_emb[Bm * Hc];
__device__ float g_prot[Bm * Hc];          // protein max-pool accum (relu >= 0)
__device__ float g_pv0[Bm * 50 * Lc];
__device__ float g_pv1[Bm * 96 * Lc];
__device__ float g_pv2[Bm * 128 * Lc];

// ---------------- init: zero the atomicMax accumulator -------------------
__global__ void k_zero_prot() {
    int i = blockIdx.x * blockDim.x + threadIdx.x;
    if (i < Bm * Hc) g_prot[i] = 0.f;
}

// ---------------- flat GEMM: C = (binput?) + A @ Bw, relu -> message ------
// M=12288, N=200(Hc). Tile 128m x 64n, 256 threads (tm 0..31, tn 0..7).
// Thread tile: 4 m (strided 32) x 8 n (4 f32x2 pairs).
// ITER=false: A=fbonds (K=50);  writes g_binput(raw) + g_message(relu)
// ITER=true : A=g_nei  (K=200); writes g_message = relu(g_binput + A@Bw)
template <int KDIM, bool ITER>
__global__ void gemm_kernel(const float* __restrict__ A, const float* __restrict__ Bw) {
    constexpr int KT = 25;
    __shared__ u64 sA2[KT * 129];                       // dup (v,v), padded rows
    __shared__ __align__(16) float sBw[KT * 64];
    int m0 = blockIdx.x * 128, n0 = blockIdx.y * 64;
    int tid = threadIdx.x, tm = tid & 31, tn = tid >> 5;

    u64 acc[4][4];
    #pragma unroll
    for (int i = 0; i < 4; i++)
        #pragma unroll
        for (int j = 0; j < 4; j++) acc[i][j] = 0ull;

    for (int k0 = 0; k0 < KDIM; k0 += KT) {
        __syncthreads();
        for (int idx = tid; idx < 128 * KT; idx += 256) {
            int mi = idx / KT, ki = idx - mi * KT;
            float v = A[(size_t)(m0 + mi) * KDIM + k0 + ki];
            sA2[ki * 129 + mi] = pack2(v, v);
        }
        for (int idx = tid; idx < KT * 64; idx += 256) {
            int k = idx >> 6, n = idx & 63;
            sBw[idx] = (n0 + n < Hc) ? Bw[(size_t)(k0 + k) * Hc + n0 + n] : 0.f;
        }
        __syncthreads();
        #pragma unroll 1
        for (int k = 0; k < KT; k++) {
            const u64* ar = sA2 + k * 129 + tm;
            u64 a0 = ar[0], a1 = ar[32], a2 = ar[64], a3 = ar[96];
            const u64* wp = (const u64*)(sBw + k * 64 + tn * 8);
            u64 w0 = wp[0], w1 = wp[1], w2 = wp[2], w3 = wp[3];
            acc[0][0] = ffma2(w0, a0, acc[0][0]); acc[0][1] = ffma2(w0, a1, acc[0][1]);
            acc[0][2] = ffma2(w0, a2, acc[0][2]); acc[0][3] = ffma2(w0, a3, acc[0][3]);
            acc[1][0] = ffma2(w1, a0, acc[1][0]); acc[1][1] = ffma2(w1, a1, acc[1][1]);
            acc[1][2] = ffma2(w1, a2, acc[1][2]); acc[1][3] = ffma2(w1, a3, acc[1][3]);
            acc[2][0] = ffma2(w2, a0, acc[2][0]); acc[2][1] = ffma2(w2, a1, acc[2][1]);
            acc[2][2] = ffma2(w2, a2, acc[2][2]); acc[2][3] = ffma2(w2, a3, acc[2][3]);
            acc[3][0] = ffma2(w3, a0, acc[3][0]); acc[3][1] = ffma2(w3, a1, acc[3][1]);
            acc[3][2] = ffma2(w3, a2, acc[3][2]); acc[3][3] = ffma2(w3, a3, acc[3][3]);
        }
    }

    if (n0 + tn * 8 >= Hc) return;   // N padding tile (n pairs all-or-nothing: Hc even)
    #pragma unroll
    for (int j = 0; j < 4; j++) {
        size_t base = (size_t)(m0 + tm + 32 * j) * Hc + n0 + tn * 8;
        u64* bp = (u64*)(g_binput + base);
        u64* mp = (u64*)(g_message + base);
        #pragma unroll
        for (int i = 0; i < 4; i++) {
            u64 s = acc[i][j];
            if (ITER) s = add2(s, bp[i]);
            else      bp[i] = s;
            float2 v = unpack2(s);
            mp[i] = pack2(fmaxf(v.x, 0.f), fmaxf(v.y, 0.f));
        }
    }
}

// ---------------- neighbor gather: nei = sum_j message[bg[j]] -------------
__global__ void k_gather(const int* __restrict__ bgraph) {
    int idx = blockIdx.x * 256 + threadIdx.x;
    if (idx >= Mrows * Hc) return;
    int m = idx / Hc, h = idx - m * Hc;
    int b = m / NBc;
    const int* bg = bgraph + m * 6;
    const float* msgB = g_message + (size_t)b * NBc * Hc + h;
    float s = 0.f;
    #pragma unroll
    for (int j = 0; j < 6; j++) s += msgB[bg[j] * Hc];
    g_nei[idx] = s;
}

// ---------------- MPNN: atom output + mean -> molecule embedding ----------
__global__ void k_out(const int* __restrict__ agraph, const float* __restrict__ fa,
                      const float* __restrict__ Wo, const float* __restrict__ Wob) {
    extern __shared__ float sm[];
    float* sMsg = sm;                         // NBc*Hc (reused as sAtom later)
    float* sNei = sm + NBc * Hc;              // NAc*Hc
    float* sFa  = sNei + NAc * Hc;            // NAc*AFc
    int b = blockIdx.x, tid = threadIdx.x;
    const float* msgB = g_message + (size_t)b * NBc * Hc;
    for (int i = tid; i < NBc * Hc; i += blockDim.x) sMsg[i] = msgB[i];
    const float* faB = fa + (size_t)b * NAc * AFc;
    for (int i = tid; i < NAc * AFc; i += blockDim.x) sFa[i] = faB[i];
    __syncthreads();
    for (int o = tid; o < NAc * Hc; o += blockDim.x) {
        int na = o / Hc, h = o - na * Hc;
        const int* ag = agraph + (b * NAc + na) * 6;
        float s = 0.f;
        #pragma unroll
        for (int j = 0; j < 6; j++) s += sMsg[ag[j] * Hc + h];
        sNei[o] = s;
    }
    __syncthreads();
    for (int o = tid; o < NAc * Hc; o += blockDim.x) {
        int na = o / Hc, h = o - na * Hc;
        float a = Wob[h];
        for (int k = 0; k < AFc; k++) a += sFa[na * AFc + k] * Wo[k * Hc + h];
        for (int k = 0; k < Hc; k++) a += sNei[na * Hc + k] * Wo[(AFc + k) * Hc + h];
        sMsg[o] = fmaxf(a, 0.f);
    }
    __syncthreads();
    for (int h = tid; h < Hc; h += blockDim.x) {
        float s = 0.f;
        for (int na = 0; na < NAc; na++) s += sMsg[na * Hc + h];
        g_emb[b * Hc + h] = s * (1.f / NAc);
    }
}

// ---------------- protein embedding gather -------------------------------
__global__ void k_embed(const int* __restrict__ seq, const float* __restrict__ E) {
    int i = blockIdx.x * blockDim.x + threadIdx.x;
    if (i >= Bm * 50 * Lc) return;
    int b = i / (50 * Lc);
    int r = i - b * (50 * Lc);
    int c = r / Lc;
    int l = r - c * Lc;
    int s = seq[b * Lc + l];
    g_pv0[i] = E[s * 50 + c];
}

// ---------------- conv1d + relu (+fused global max), FFMA2 ----------------
// Block tile: CoT co x 128 l.  Threads NT = 4*CoT: (tco 0..CoT/8-1, tl 0..31).
// Thread tile: 8 co (4 f32x2 pairs) x 4 l (strided 32).
// smem: sIn2 = duplicated (v,v) u64 input tile [CI_TILE][TLH];
//       sW   = weights transposed [CI_TILE][K][CoT] (co contiguous -> u64 pairs).
// Exact tilings chosen per layer: no co raggedness.
template <int CIN, int COUT, int K, int CI_TILE, int CoT, int NT, bool MAXPOOL>
__global__ void conv_kernel(const float* __restrict__ in, const float* __restrict__ w,
                            const float* __restrict__ bias, float* __restrict__ out,
                            float* __restrict__ pmax) {
    constexpr int TL = 128, PAD = K / 2, TLH = TL + K - 1;
    extern __shared__ char smraw[];
    u64* sIn2 = (u64*)smraw;                        // CI_TILE*TLH u64
    float* sW = (float*)(sIn2 + CI_TILE * TLH);     // CI_TILE*K*CoT
    float* sB = sW + CI_TILE * K * CoT;             // CoT
    int b = blockIdx.z, coBase = blockIdx.y * CoT, lBase = blockIdx.x * TL;
    int tid = threadIdx.x, tco = tid >> 5, tl = tid & 31;
    if (tid < CoT) sB[tid] = bias[coBase + tid];
    __syncthreads();
    int co0 = tco * 8;
    u64 acc[4][4];
    #pragma unroll
    for (int i = 0; i < 4; i++) {
        u64 bv = pack2(sB[co0 + 2 * i], sB[co0 + 2 * i + 1]);
        #pragma unroll
        for (int j = 0; j < 4; j++) acc[i][j] = bv;
    }

    const float* inB = in + (size_t)b * CIN * Lc;
    for (int ct = 0; ct < CIN; ct += CI_TILE) {
        __syncthreads();
        for (int i = tid; i < CI_TILE * TLH; i += NT) {
            int ci = i / TLH, p = i - ci * TLH;
            int gl = lBase - PAD + p;
            float v = (gl >= 0 && gl < Lc) ? inB[(size_t)(ct + ci) * Lc + gl] : 0.f;
            sIn2[i] = pack2(v, v);
        }
        for (int i = tid; i < CI_TILE * K * CoT; i += NT) {
            int co = i % CoT; int r = i / CoT; int t = r % K; int ci = r / K;
            sW[i] = w[((size_t)(coBase + co) * CIN + ct + ci) * K + t];
        }
        __syncthreads();
        #pragma unroll 1
        for (int ci = 0; ci < CI_TILE; ci++) {
            const u64* xr = sIn2 + ci * TLH + tl;
            const float* wr = sW + ci * K * CoT + co0;
            #pragma unroll
            for (int t = 0; t < K; t++) {
                const u64* wp = (const u64*)(wr + t * CoT);
                u64 w0 = wp[0], w1 = wp[1], w2 = wp[2], w3 = wp[3];
                u64 x0 = xr[t], x1 = xr[t + 32], x2 = xr[t + 64], x3 = xr[t + 96];
                acc[0][0] = ffma2(w0, x0, acc[0][0]); acc[0][1] = ffma2(w0, x1, acc[0][1]);
                acc[0][2] = ffma2(w0, x2, acc[0][2]); acc[0][3] = ffma2(w0, x3, acc[0][3]);
                acc[1][0] = ffma2(w1, x0, acc[1][0]); acc[1][1] = ffma2(w1, x1, acc[1][1]);
                acc[1][2] = ffma2(w1, x2, acc[1][2]); acc[1][3] = ffma2(w1, x3, acc[1][3]);
                acc[2][0] = ffma2(w2, x0, acc[2][0]); acc[2][1] = ffma2(w2, x1, acc[2][1]);
                acc[2][2] = ffma2(w2, x2, acc[2][2]); acc[2][3] = ffma2(w2, x3, acc[2][3]);
                acc[3][0] = ffma2(w3, x0, acc[3][0]); acc[3][1] = ffma2(w3, x1, acc[3][1]);
                acc[3][2] = ffma2(w3, x2, acc[3][2]); acc[3][3] = ffma2(w3, x3, acc[3][3]);
            }
        }
    }

    if (MAXPOOL) {
        float mx[8];
        #pragma unroll
        for (int i = 0; i < 4; i++) {
            float m0 = 0.f, m1 = 0.f;
            #pragma unroll
            for (int j = 0; j < 4; j++) {
                int l = lBase + tl + 32 * j;
                if (l < Lc) {
                    float2 v = unpack2(acc[i][j]);
                    m0 = fmaxf(m0, v.x);
                    m1 = fmaxf(m1, v.y);
                }
            }
            mx[2 * i] = m0; mx[2 * i + 1] = m1;
        }
        #pragma unroll
        for (int off = 16; off; off >>= 1)
            #pragma unroll
            for (int c = 0; c < 8; c++)
                mx[c] = fmaxf(mx[c], __shfl_xor_sync(0xffffffffu, mx[c], off));
        if (tl == 0) {
            #pragma unroll
            for (int c = 0; c < 8; c++)
                atomicMax((int*)(pmax + b * COUT + coBase + co0 + c), __float_as_int(fmaxf(mx[c], 0.f)));
        }
    } else {
        float* outB = out + (size_t)b * COUT * Lc;
        #pragma unroll
        for (int i = 0; i < 4; i++) {
            int co = coBase + co0 + 2 * i;
            #pragma unroll
            for (int j = 0; j < 4; j++) {
                int l = lBase + tl + 32 * j;
                if (l < Lc) {
                    float2 v = unpack2(acc[i][j]);
                    outB[(size_t)co * Lc + l] = fmaxf(v.x, 0.f);
                    outB[(size_t)(co + 1) * Lc + l] = fmaxf(v.y, 0.f);
                }
            }
        }
    }
}

// ---------------- FC head: 400 -> 200 -> 100 -> 1 ------------------------
__global__ void k_fc(const float* __restrict__ w0, const float* __restrict__ b0,
                     const float* __restrict__ w1, const float* __restrict__ b1,
                     const float* __restrict__ w2, const float* __restrict__ b2,
                     float* __restrict__ out) {
    __shared__ float sx[400];
    __shared__ float sy0[200];
    __shared__ float sy1[100];
    int b = blockIdx.x, tid = threadIdx.x;
    for (int k = tid; k < 400; k += blockDim.x)
        sx[k] = (k < 200) ? g_emb[b * 200 + k] : g_prot[b * 200 + (k - 200)];
    __syncthreads();
    for (int j = tid; j < 200; j += blockDim.x) {
        float a = b0[j];
        for (int k = 0; k < 400; k++) a += sx[k] * w0[k * 200 + j];
        sy0[j] = fmaxf(a, 0.f);
    }
    __syncthreads();
    for (int j = tid; j < 100; j += blockDim.x) {
        float a = b1[j];
        for (int k = 0; k < 200; k++) a += sy0[k] * w1[k * 100 + j];
        sy1[j] = fmaxf(a, 0.f);
    }
    __syncthreads();
    if (tid == 0) {
        float a = b2[0];
        for (int k = 0; k < 100; k++) a += sy1[k] * w2[k];
        out[b] = a;
    }
}

// ---------------- launch --------------------------------------------------
extern "C" void kernel_launch(void* const* d_in, const int* in_sizes, int n_in,
                              void* d_out, int out_size) {
    const float* fatoms = (const float*)d_in[0];
    const float* fbonds = (const float*)d_in[1];
    const int* agraph = (const int*)d_in[2];
    const int* bgraph = (const int*)d_in[3];
    const int* pseq = (const int*)d_in[4];
    const float* W_i = (const float*)d_in[5];
    const float* W_h = (const float*)d_in[6];
    const float* W_o_w = (const float*)d_in[7];
    const float* W_o_b = (const float*)d_in[8];
    const float* Ep = (const float*)d_in[9];
    const float* c0w = (const float*)d_in[10];
    const float* c0b = (const float*)d_in[11];
    const float* c1w = (const float*)d_in[12];
    const float* c1b = (const float*)d_in[13];
    const float* c2w = (const float*)d_in[14];
    const float* c2b = (const float*)d_in[15];
    const float* f0w = (const float*)d_in[16];
    const float* f0b = (const float*)d_in[17];
    const float* f1w = (const float*)d_in[18];
    const float* f1b = (const float*)d_in[19];
    const float* f2w = (const float*)d_in[20];
    const float* f2b = (const float*)d_in[21];
    float* out = (float*)d_out;

    const int smem_out = (NBc * Hc + NAc * Hc + NAc * AFc) * 4;
    const int smem_c0 = (50 * 130) * 8 + (50 * 3 * 48) * 4 + 48 * 4;     // 80992
    const int smem_c1 = (32 * 132) * 8 + (32 * 5 * 64) * 4 + 64 * 4;     // 75008
    const int smem_c2 = (32 * 134) * 8 + (32 * 7 * 40) * 4 + 40 * 4;     // 70304

    // Resolve REAL device addresses of __device__ globals passed as args.
    static float *p_pv0 = nullptr, *p_pv1 = nullptr, *p_pv2 = nullptr,
                 *p_prot = nullptr, *p_nei = nullptr;
    static bool init_done = false;
    if (!init_done) {
        cudaGetSymbolAddress((void**)&p_pv0, g_pv0);
        cudaGetSymbolAddress((void**)&p_pv1, g_pv1);
        cudaGetSymbolAddress((void**)&p_pv2, g_pv2);
        cudaGetSymbolAddress((void**)&p_prot, g_prot);
        cudaGetSymbolAddress((void**)&p_nei, g_nei);
        cudaFuncSetAttribute(k_out, cudaFuncAttributeMaxDynamicSharedMemorySize, smem_out);
        cudaFuncSetAttribute(conv_kernel<50, 96, 3, 50, 48, 192, false>,
                             cudaFuncAttributeMaxDynamicSharedMemorySize, smem_c0);
        cudaFuncSetAttribute(conv_kernel<96, 128, 5, 32, 64, 256, false>,
                             cudaFuncAttributeMaxDynamicSharedMemorySize, smem_c1);
        cudaFuncSetAttribute(conv_kernel<128, 200, 7, 32, 40, 160, true>,
                             cudaFuncAttributeMaxDynamicSharedMemorySize, smem_c2);
        init_done = true;
    }

    k_zero_prot<<<(Bm * Hc + 255) / 256, 256>>>();

    // ---- MPNN ----
    {
        dim3 g(Mrows / 128, 4);
        gemm_kernel<50, false><<<g, 256>>>(fbonds, W_i);     // binput + relu->message
        int gg = (Mrows * Hc + 255) / 256;
        k_gather<<<gg, 256>>>(bgraph);
        gemm_kernel<200, true><<<g, 256>>>(p_nei, W_h);      // message iter 1
        k_gather<<<gg, 256>>>(bgraph);
        gemm_kernel<200, true><<<g, 256>>>(p_nei, W_h);      // message iter 2
    }
    k_out<<<Bm, 256, smem_out>>>(agraph, fatoms, W_o_w, W_o_b);

    // ---- protein tower ----
    k_embed<<<(Bm * 50 * Lc + 255) / 256, 256>>>(pseq, Ep);
    {
        dim3 g(8, 2, Bm);   // 96 = 2 x 48
        conv_kernel<50, 96, 3, 50, 48, 192, false><<<g, 192, smem_c0>>>(p_pv0, c0w, c0b, p_pv1, nullptr);
    }
    {
        dim3 g(8, 2, Bm);   // 128 = 2 x 64
        conv_kernel<96, 128, 5, 32, 64, 256, false><<<g, 256, smem_c1>>>(p_pv1, c1w, c1b, p_pv2, nullptr);
    }
    {
        dim3 g(8, 5, Bm);   // 200 = 5 x 40
        conv_kernel<128, 200, 7, 32, 40, 160, true><<<g, 160, smem_c2>>>(p_pv2, c2w, c2b, nullptr, p_prot);
    }

    // ---- FC head ----
    k_fc<<<Bm, 256>>>(f0w, f0b, f1w, f1b, f2w, f2b, out);
}

// round 5
// speedup vs baseline: 1.7494x; 1.2384x over previous
#include <cuda_runtime.h>
#include <cstdint>

#define Bm 128
#define NAc 48
#define NBc 96
#define Hc 200
#define AFc 39
#define BFc 50      // ATOM_FDIM + BOND_FDIM
#define Lc 1000
#define Mrows (Bm * NBc)   // 12288
#define Marows (Bm * NAc)  // 6144
#define KAo 240            // padded 39+200+1

typedef unsigned long long u64;

// ---------------- f32x2 helpers (sm_103a FFMA2 via PTX) -------------------
__device__ __forceinline__ u64 pack2(float a, float b) {
    u64 r; asm("mov.b64 %0, {%1, %2};" : "=l"(r) : "f"(a), "f"(b)); return r;
}
__device__ __forceinline__ float2 unpack2(u64 a) {
    float2 v; asm("mov.b64 {%0, %1}, %2;" : "=f"(v.x), "=f"(v.y) : "l"(a)); return v;
}
__device__ __forceinline__ u64 ffma2(u64 a, u64 b, u64 c) {
    u64 d; asm("fma.rn.f32x2 %0, %1, %2, %3;" : "=l"(d) : "l"(a), "l"(b), "l"(c)); return d;
}
__device__ __forceinline__ u64 add2(u64 a, u64 b) {
    u64 d; asm("add.rn.f32x2 %0, %1, %2;" : "=l"(d) : "l"(a), "l"(b)); return d;
}

// ---------------- scratch (device globals; no allocation) ----------------
__device__ float g_binput[Mrows * Hc];
__device__ float g_message[Mrows * Hc];
__device__ float g_nei[Mrows * Hc];
__device__ float g_ain[Marows * KAo];
__device__ float g_wo[KAo * Hc];
__device__ float g_atomh[Marows * Hc];
__device__ float g_emb[Bm * Hc];
__device__ float g_prot[Bm * Hc];          // protein max-pool accum (relu >= 0)
__device__ float g_pv0[Bm * 50 * Lc];
__device__ float g_pv1[Bm * 96 * Lc];
__device__ float g_pv2[Bm * 128 * Lc];

// ---------------- init: zero the atomicMax accumulator -------------------
__global__ void k_zero_prot() {
    int i = blockIdx.x * blockDim.x + threadIdx.x;
    if (i < Bm * Hc) g_prot[i] = 0.f;
}

// ---------------- flat GEMM, n-paired FFMA2 -------------------------------
// Tile 128m x 64n, 256 threads. Thread: 4m (strided 32) x 8n (4 f32x2 pairs).
// MODE 0: Craw = A@Bw (raw), Cout = relu(raw)          (binput)
// MODE 1: Cout = relu(Craw + A@Bw)                      (message iter)
// MODE 2: Cout = relu(A@Bw + bias[n])                   (atom output)
template <int KDIM, int KT, int MODE>
__global__ void gemm_kernel(const float* __restrict__ A, const float* __restrict__ Bw,
                            const float* __restrict__ bias,
                            float* __restrict__ Craw, float* __restrict__ Cout) {
    __shared__ u64 sA2[KT * 129];                       // dup (v,v), padded rows
    __shared__ __align__(16) float sBw[KT * 64];
    int m0 = blockIdx.x * 128, n0 = blockIdx.y * 64;
    int tid = threadIdx.x, tm = tid & 31, tn = tid >> 5;

    u64 acc[4][4];
    #pragma unroll
    for (int i = 0; i < 4; i++)
        #pragma unroll
        for (int j = 0; j < 4; j++) acc[i][j] = 0ull;

    for (int k0 = 0; k0 < KDIM; k0 += KT) {
        __syncthreads();
        for (int idx = tid; idx < 128 * KT; idx += 256) {
            int mi = idx / KT, ki = idx - mi * KT;
            float v = A[(size_t)(m0 + mi) * KDIM + k0 + ki];
            sA2[ki * 129 + mi] = pack2(v, v);
        }
        for (int idx = tid; idx < KT * 64; idx += 256) {
            int k = idx >> 6, n = idx & 63;
            sBw[idx] = (n0 + n < Hc) ? Bw[(size_t)(k0 + k) * Hc + n0 + n] : 0.f;
        }
        __syncthreads();
        #pragma unroll 1
        for (int k = 0; k < KT; k++) {
            const u64* ar = sA2 + k * 129 + tm;
            u64 a0 = ar[0], a1 = ar[32], a2 = ar[64], a3 = ar[96];
            const u64* wp = (const u64*)(sBw + k * 64 + tn * 8);
            u64 w0 = wp[0], w1 = wp[1], w2 = wp[2], w3 = wp[3];
            acc[0][0] = ffma2(w0, a0, acc[0][0]); acc[0][1] = ffma2(w0, a1, acc[0][1]);
            acc[0][2] = ffma2(w0, a2, acc[0][2]); acc[0][3] = ffma2(w0, a3, acc[0][3]);
            acc[1][0] = ffma2(w1, a0, acc[1][0]); acc[1][1] = ffma2(w1, a1, acc[1][1]);
            acc[1][2] = ffma2(w1, a2, acc[1][2]); acc[1][3] = ffma2(w1, a3, acc[1][3]);
            acc[2][0] = ffma2(w2, a0, acc[2][0]); acc[2][1] = ffma2(w2, a1, acc[2][1]);
            acc[2][2] = ffma2(w2, a2, acc[2][2]); acc[2][3] = ffma2(w2, a3, acc[2][3]);
            acc[3][0] = ffma2(w3, a0, acc[3][0]); acc[3][1] = ffma2(w3, a1, acc[3][1]);
            acc[3][2] = ffma2(w3, a2, acc[3][2]); acc[3][3] = ffma2(w3, a3, acc[3][3]);
        }
    }

    int nb = n0 + tn * 8;
    if (nb >= Hc) return;   // Hc even: pair groups all-or-nothing
    u64 bp2[4];
    if (MODE == 2) {
        #pragma unroll
        for (int i = 0; i < 4; i++) bp2[i] = pack2(bias[nb + 2 * i], bias[nb + 2 * i + 1]);
    }
    #pragma unroll
    for (int j = 0; j < 4; j++) {
        size_t base = (size_t)(m0 + tm + 32 * j) * Hc + nb;
        u64* rp = (MODE == 2) ? nullptr : (u64*)(Craw + base);
        u64* op = (u64*)(Cout + base);
        #pragma unroll
        for (int i = 0; i < 4; i++) {
            u64 s = acc[i][j];
            if (MODE == 1) s = add2(s, rp[i]);
            if (MODE == 2) s = add2(s, bp2[i]);
            if (MODE == 0) rp[i] = s;
            float2 v = unpack2(s);
            op[i] = pack2(fmaxf(v.x, 0.f), fmaxf(v.y, 0.f));
        }
    }
}

// ---------------- neighbor gather: nei = sum_j message[bg[j]] -------------
__global__ void k_gather(const int* __restrict__ bgraph) {
    int idx = blockIdx.x * 256 + threadIdx.x;
    if (idx >= Mrows * Hc) return;
    int m = idx / Hc, h = idx - m * Hc;
    int b = m / NBc;
    const int* bg = bgraph + m * 6;
    const float* msgB = g_message + (size_t)b * NBc * Hc + h;
    float s = 0.f;
    #pragma unroll
    for (int j = 0; j < 6; j++) s += msgB[bg[j] * Hc];
    g_nei[idx] = s;
}

// ---------------- atom input build: [fa | gather(message) | 0] ------------
__global__ void k_gather_atoms(const int* __restrict__ agraph, const float* __restrict__ fa) {
    int idx = blockIdx.x * 256 + threadIdx.x;
    if (idx >= Marows * KAo) return;
    int m = idx / KAo, c = idx - m * KAo;
    int b = m / NAc;
    float v = 0.f;
    if (c < AFc) {
        v = fa[(size_t)m * AFc + c];
    } else if (c < AFc + Hc) {
        int h = c - AFc;
        const int* ag = agraph + m * 6;
        const float* msgB = g_message + (size_t)b * NBc * Hc + h;
        #pragma unroll
        for (int j = 0; j < 6; j++) v += msgB[ag[j] * Hc];
    }
    g_ain[idx] = v;
}

// ---------------- pad W_o (239 x 200) -> (240 x 200) ----------------------
__global__ void k_pad_w(const float* __restrict__ Wo) {
    int idx = blockIdx.x * 256 + threadIdx.x;
    if (idx >= KAo * Hc) return;
    int r = idx / Hc, h = idx - r * Hc;
    g_wo[idx] = (r < AFc + Hc) ? Wo[(size_t)r * Hc + h] : 0.f;
}

// ---------------- mean over atoms -> molecule embedding -------------------
__global__ void k_mean() {
    int b = blockIdx.x, h = threadIdx.x;
    if (h >= Hc) return;
    const float* ah = g_atomh + (size_t)b * NAc * Hc + h;
    float s = 0.f;
    for (int na = 0; na < NAc; na++) s += ah[(size_t)na * Hc];
    g_emb[b * Hc + h] = s * (1.f / NAc);
}

// ---------------- protein embedding gather -------------------------------
__global__ void k_embed(const int* __restrict__ seq, const float* __restrict__ E) {
    int i = blockIdx.x * blockDim.x + threadIdx.x;
    if (i >= Bm * 50 * Lc) return;
    int b = i / (50 * Lc);
    int r = i - b * (50 * Lc);
    int c = r / Lc;
    int l = r - c * Lc;
    int s = seq[b * Lc + l];
    g_pv0[i] = E[s * 50 + c];
}

// ---------------- conv1d + relu (+fused global max), l-paired FFMA2 -------
// Block tile: CoT co x 256 l. Threads NT = (CoT/8)*32: warp tco covers 8 co,
// lane tl covers l-pairs at l = 2*(tl + 32j), j=0..3.
// smem: sInE[p]=(x[2p],x[2p+1]), sInO[p]=(x[2p+1],x[2p+2]) (even/odd shifted
// copies -> every tap t is one aligned LDS.64, all bytes unique);
// sW2[ci][t][co] = (w,w) duplicated (warp-broadcast -> free).
// 32 independent FFMA2 per (ci,t) per thread.
template <int CIN, int COUT, int K, int CI_TILE, int CoT, int NT, bool MAXPOOL>
__global__ void __launch_bounds__(NT) conv_kernel(
        const float* __restrict__ in, const float* __restrict__ w,
        const float* __restrict__ bias, float* __restrict__ out,
        float* __restrict__ pmax) {
    constexpr int TL = 256, PAD = K / 2, NP = (TL + K - 1) / 2 + 2;
    extern __shared__ char smraw[];
    u64* sInE = (u64*)smraw;                        // CI_TILE*NP
    u64* sInO = sInE + CI_TILE * NP;                // CI_TILE*NP
    u64* sW2 = sInO + CI_TILE * NP;                 // CI_TILE*K*CoT
    int b = blockIdx.z, coBase = blockIdx.y * CoT, lBase = blockIdx.x * TL;
    int tid = threadIdx.x, tco = tid >> 5, tl = tid & 31;
    int co0 = tco * 8;

    u64 acc[8][4];
    #pragma unroll
    for (int i = 0; i < 8; i++) {
        float bv = bias[coBase + co0 + i];
        u64 bp = pack2(bv, bv);
        #pragma unroll
        for (int j = 0; j < 4; j++) acc[i][j] = bp;
    }

    const float* inB = in + (size_t)b * CIN * Lc;
    for (int ct = 0; ct < CIN; ct += CI_TILE) {
        __syncthreads();
        for (int i = tid; i < CI_TILE * NP; i += NT) {
            int ci = i / NP, p = i - ci * NP;
            int gl = lBase - PAD + 2 * p;
            const float* row = inB + (size_t)(ct + ci) * Lc;
            float v0 = (gl >= 0 && gl < Lc) ? row[gl] : 0.f;
            float v1 = (gl + 1 >= 0 && gl + 1 < Lc) ? row[gl + 1] : 0.f;
            float v2 = (gl + 2 >= 0 && gl + 2 < Lc) ? row[gl + 2] : 0.f;
            sInE[i] = pack2(v0, v1);
            sInO[i] = pack2(v1, v2);
        }
        for (int i = tid; i < CI_TILE * K * CoT; i += NT) {
            int co = i % CoT; int r = i / CoT; int t = r % K; int ci = r / K;
            float wv = w[((size_t)(coBase + co) * CIN + ct + ci) * K + t];
            sW2[i] = pack2(wv, wv);
        }
        __syncthreads();
        #pragma unroll 1
        for (int ci = 0; ci < CI_TILE; ci++) {
            const u64* rE = sInE + ci * NP + tl;
            const u64* rO = sInO + ci * NP + tl;
            const u64* wr = sW2 + (size_t)ci * K * CoT + co0;
            #pragma unroll
            for (int t = 0; t < K; t++) {
                const u64* xr = ((t & 1) ? rO : rE) + (t >> 1);
                u64 x0 = xr[0], x1 = xr[32], x2 = xr[64], x3 = xr[96];
                u64 wv[8];
                #pragma unroll
                for (int i = 0; i < 8; i++) wv[i] = wr[t * CoT + i];
                #pragma unroll
                for (int i = 0; i < 8; i++) {
                    acc[i][0] = ffma2(wv[i], x0, acc[i][0]);
                    acc[i][1] = ffma2(wv[i], x1, acc[i][1]);
                    acc[i][2] = ffma2(wv[i], x2, acc[i][2]);
                    acc[i][3] = ffma2(wv[i], x3, acc[i][3]);
                }
            }
        }
    }

    if (MAXPOOL) {
        float mx[8];
        #pragma unroll
        for (int i = 0; i < 8; i++) {
            float m = 0.f;
            #pragma unroll
            for (int j = 0; j < 4; j++) {
                int l = lBase + 2 * (tl + 32 * j);
                if (l < Lc) {
                    float2 v = unpack2(acc[i][j]);
                    m = fmaxf(m, fmaxf(v.x, v.y));
                }
            }
            mx[i] = m;   // relu folded: m >= 0
        }
        #pragma unroll
        for (int off = 16; off; off >>= 1)
            #pragma unroll
            for (int i = 0; i < 8; i++)
                mx[i] = fmaxf(mx[i], __shfl_xor_sync(0xffffffffu, mx[i], off));
        if (tl == 0) {
            #pragma unroll
            for (int i = 0; i < 8; i++)
                atomicMax((int*)(pmax + b * COUT + coBase + co0 + i), __float_as_int(mx[i]));
        }
    } else {
        float* outB = out + (size_t)b * COUT * Lc;
        #pragma unroll
        for (int i = 0; i < 8; i++) {
            float* orow = outB + (size_t)(coBase + co0 + i) * Lc;
            #pragma unroll
            for (int j = 0; j < 4; j++) {
                int l = lBase + 2 * (tl + 32 * j);
                if (l < Lc) {   // Lc even: pair fully valid
                    float2 v = unpack2(acc[i][j]);
                    *(u64*)(orow + l) = pack2(fmaxf(v.x, 0.f), fmaxf(v.y, 0.f));
                }
            }
        }
    }
}

// ---------------- FC head: 400 -> 200 -> 100 -> 1 ------------------------
__global__ void k_fc(const float* __restrict__ w0, const float* __restrict__ b0,
                     const float* __restrict__ w1, const float* __restrict__ b1,
                     const float* __restrict__ w2, const float* __restrict__ b2,
                     float* __restrict__ out) {
    __shared__ float sx[400];
    __shared__ float sy0[200];
    __shared__ float sy1[100];
    int b = blockIdx.x, tid = threadIdx.x;
    for (int k = tid; k < 400; k += blockDim.x)
        sx[k] = (k < 200) ? g_emb[b * 200 + k] : g_prot[b * 200 + (k - 200)];
    __syncthreads();
    for (int j = tid; j < 200; j += blockDim.x) {
        float a = b0[j];
        for (int k = 0; k < 400; k++) a += sx[k] * w0[k * 200 + j];
        sy0[j] = fmaxf(a, 0.f);
    }
    __syncthreads();
    for (int j = tid; j < 100; j += blockDim.x) {
        float a = b1[j];
        for (int k = 0; k < 200; k++) a += sy0[k] * w1[k * 100 + j];
        sy1[j] = fmaxf(a, 0.f);
    }
    __syncthreads();
    if (tid == 0) {
        float a = b2[0];
        for (int k = 0; k < 100; k++) a += sy1[k] * w2[k];
        out[b] = a;
    }
}

// ---------------- launch --------------------------------------------------
extern "C" void kernel_launch(void* const* d_in, const int* in_sizes, int n_in,
                              void* d_out, int out_size) {
    const float* fatoms = (const float*)d_in[0];
    const float* fbonds = (const float*)d_in[1];
    const int* agraph = (const int*)d_in[2];
    const int* bgraph = (const int*)d_in[3];
    const int* pseq = (const int*)d_in[4];
    const float* W_i = (const float*)d_in[5];
    const float* W_h = (const float*)d_in[6];
    const float* W_o_w = (const float*)d_in[7];
    const float* W_o_b = (const float*)d_in[8];
    const float* Ep = (const float*)d_in[9];
    const float* c0w = (const float*)d_in[10];
    const float* c0b = (const float*)d_in[11];
    const float* c1w = (const float*)d_in[12];
    const float* c1b = (const float*)d_in[13];
    const float* c2w = (const float*)d_in[14];
    const float* c2b = (const float*)d_in[15];
    const float* f0w = (const float*)d_in[16];
    const float* f0b = (const float*)d_in[17];
    const float* f1w = (const float*)d_in[18];
    const float* f1b = (const float*)d_in[19];
    const float* f2w = (const float*)d_in[20];
    const float* f2b = (const float*)d_in[21];
    float* out = (float*)d_out;

    // conv smem: (2*CI_TILE*NP + CI_TILE*K*CoT) * 8 bytes
    const int smem_c0 = (2 * 25 * 131 + 25 * 3 * 48) * 8;   // 81200
    const int smem_c1 = (2 * 16 * 132 + 16 * 5 * 64) * 8;   // 74752
    const int smem_c2 = (2 * 16 * 133 + 16 * 7 * 40) * 8;   // 69888

    // Resolve REAL device addresses of __device__ globals passed as args.
    static float *p_pv0 = nullptr, *p_pv1 = nullptr, *p_pv2 = nullptr,
                 *p_prot = nullptr, *p_nei = nullptr, *p_binput = nullptr,
                 *p_message = nullptr, *p_ain = nullptr, *p_wo = nullptr,
                 *p_atomh = nullptr;
    static bool init_done = false;
    if (!init_done) {
        cudaGetSymbolAddress((void**)&p_pv0, g_pv0);
        cudaGetSymbolAddress((void**)&p_pv1, g_pv1);
        cudaGetSymbolAddress((void**)&p_pv2, g_pv2);
        cudaGetSymbolAddress((void**)&p_prot, g_prot);
        cudaGetSymbolAddress((void**)&p_nei, g_nei);
        cudaGetSymbolAddress((void**)&p_binput, g_binput);
        cudaGetSymbolAddress((void**)&p_message, g_message);
        cudaGetSymbolAddress((void**)&p_ain, g_ain);
        cudaGetSymbolAddress((void**)&p_wo, g_wo);
        cudaGetSymbolAddress((void**)&p_atomh, g_atomh);
        cudaFuncSetAttribute(conv_kernel<50, 96, 3, 25, 48, 192, false>,
                             cudaFuncAttributeMaxDynamicSharedMemorySize, smem_c0);
        cudaFuncSetAttribute(conv_kernel<96, 128, 5, 16, 64, 256, false>,
                             cudaFuncAttributeMaxDynamicSharedMemorySize, smem_c1);
        cudaFuncSetAttribute(conv_kernel<128, 200, 7, 16, 40, 160, true>,
                             cudaFuncAttributeMaxDynamicSharedMemorySize, smem_c2);
        init_done = true;
    }

    k_zero_prot<<<(Bm * Hc + 255) / 256, 256>>>();
    k_pad_w<<<(KAo * Hc + 255) / 256, 256>>>(W_o_w);

    // ---- MPNN ----
    {
        dim3 g(Mrows / 128, 4);
        gemm_kernel<50, 25, 0><<<g, 256>>>(fbonds, W_i, nullptr, p_binput, p_message);
        int gg = (Mrows * Hc + 255) / 256;
        k_gather<<<gg, 256>>>(bgraph);
        gemm_kernel<200, 25, 1><<<g, 256>>>(p_nei, W_h, nullptr, p_binput, p_message);
        k_gather<<<gg, 256>>>(bgraph);
        gemm_kernel<200, 25, 1><<<g, 256>>>(p_nei, W_h, nullptr, p_binput, p_message);
    }
    k_gather_atoms<<<(Marows * KAo + 255) / 256, 256>>>(agraph, fatoms);
    {
        dim3 g(Marows / 128, 4);
        gemm_kernel<KAo, 24, 2><<<g, 256>>>(p_ain, p_wo, W_o_b, nullptr, p_atomh);
    }
    k_mean<<<Bm, 224>>>();

    // ---- protein tower ----
    k_embed<<<(Bm * 50 * Lc + 255) / 256, 256>>>(pseq, Ep);
    {
        dim3 g(4, 2, Bm);   // 96 = 2 x 48
        conv_kernel<50, 96, 3, 25, 48, 192, false><<<g, 192, smem_c0>>>(p_pv0, c0w, c0b, p_pv1, nullptr);
    }
    {
        dim3 g(4, 2, Bm);   // 128 = 2 x 64
        conv_kernel<96, 128, 5, 16, 64, 256, false><<<g, 256, smem_c1>>>(p_pv1, c1w, c1b, p_pv2, nullptr);
    }
    {
        dim3 g(4, 5, Bm);   // 200 = 5 x 40
        conv_kernel<128, 200, 7, 16, 40, 160, true><<<g, 160, smem_c2>>>(p_pv2, c2w, c2b, nullptr, p_prot);
    }

    // ---- FC head ----
    k_fc<<<Bm, 256>>>(f0w, f0b, f1w, f1b, f2w, f2b, out);
}